// round 5
// baseline (speedup 1.0000x reference)
#include <cuda_runtime.h>
#include <math.h>
#include <stdint.h>
#include <stddef.h>

typedef unsigned long long u64;

// Problem dims
#define BB    64
#define TT    512
#define EE    768
#define HH    512
#define G3    1536
#define NF    256
#define MALL  (BB*TT)          // 32768

// -------- recurrence persistent-kernel config --------
#define NBLK      128          // co-resident worker CTAs
#define REDS      392          // red stride (mod 32 != 0 -> conflict-free)
#define RSM_FLOATS (8*512 + 8*REDS)
#define RSM_BYTES  (RSM_FLOATS*4)   // 28928 B

// ----------------- device scratch (statics; no cudaMalloc allowed) ----------
__device__ float g_Gi[(size_t)MALL * G3];      // reused per GRU pass
__device__ float g_seq0[(size_t)MALL * HH];    // selector hist, later out1
__device__ float g_seq1[(size_t)MALL * HH];    // out0
__device__ float g_newemb[(size_t)MALL * EE];
__device__ float g_U[(size_t)MALL * (NF*5)];   // conv GEMM out (reused)
__device__ float g_WT[G3 * EE];                // transposed weights scratch
__device__ float g_h[2][BB * HH];              // hidden-state ping-pong
__device__ int   g_sel[BB * TT];
__device__ int   g_order[BB * TT];
__device__ int   g_nsel[BB];
__device__ float g_pooled[BB * 3 * NF];
__device__ unsigned g_bars[8 * 32];            // 8 group counters, 128B apart

// ----------------------------- f32x2 helpers --------------------------------
__device__ __forceinline__ void fma2(u64& d, u64 a, u64 b) {
    asm("fma.rn.f32x2 %0,%1,%2,%0;" : "+l"(d) : "l"(a), "l"(b));
}
__device__ __forceinline__ u64 add2(u64 a, u64 b) {
    u64 r; asm("add.rn.f32x2 %0,%1,%2;" : "=l"(r) : "l"(a), "l"(b)); return r;
}
__device__ __forceinline__ float2 unpk(u64 v) {
    float2 r; asm("mov.b64 {%0,%1},%2;" : "=f"(r.x), "=f"(r.y) : "l"(v)); return r;
}
__device__ __forceinline__ u64 dup2(unsigned v) {
    u64 r; asm("mov.b64 %0,{%1,%1};" : "=l"(r) : "r"(v)); return r;
}
__device__ __forceinline__ u64 shx16(u64 v) {
    unsigned lo = (unsigned)v, hi = (unsigned)(v >> 32);
    lo = __shfl_xor_sync(0xffffffffu, lo, 16);
    hi = __shfl_xor_sync(0xffffffffu, hi, 16);
    return ((u64)hi << 32) | (u64)lo;
}
// release/acquire barrier primitives
__device__ __forceinline__ unsigned ld_acq(const unsigned* p) {
    unsigned v;
    asm volatile("ld.acquire.gpu.global.u32 %0,[%1];" : "=r"(v) : "l"(p));
    return v;
}
__device__ __forceinline__ void red_rel(unsigned* p) {
    asm volatile("red.release.gpu.global.add.u32 [%0],1;" :: "l"(p));
}

// ---------------------------------------------------------------------------
__global__ void k_reset() {
    int i = blockIdx.x * blockDim.x + threadIdx.x;
    if (i < 8 * 32) g_bars[i] = 0u;
    if (i < 2 * BB * HH) ((float*)g_h)[i] = 0.f;
}
__global__ void k_zero_pooled() {
    int i = blockIdx.x * blockDim.x + threadIdx.x;
    if (i < BB * 3 * NF) g_pooled[i] = 0.f;
}

// ---------------------------------------------------------------------------
// generic transpose: dst[C][R] = src[R][C]   (R, C multiples of 32)
// ---------------------------------------------------------------------------
__global__ void k_transpose(float* dst, const float* src, int R, int C) {
    __shared__ float tile[32][33];
    int c0 = blockIdx.x * 32, r0 = blockIdx.y * 32;
    int tx = threadIdx.x, ty = threadIdx.y;
    #pragma unroll
    for (int i = 0; i < 32; i += 8)
        tile[ty + i][tx] = src[(size_t)(r0 + ty + i) * C + c0 + tx];
    __syncthreads();
    #pragma unroll
    for (int i = 0; i < 32; i += 8)
        dst[(size_t)(c0 + ty + i) * R + r0 + tx] = tile[tx][ty + i];
}

// ---------------------------------------------------------------------------
// GEMM (f32x2): C[M][N] = A[M][K] @ BT[K][N] (+ bias[n]).
// 256x128 tile, 16-k slab, 256 threads, double-buffered smem.
// ---------------------------------------------------------------------------
__global__ __launch_bounds__(256, 1)
void k_gemm(float* __restrict__ C, const float* __restrict__ A,
            const float* __restrict__ BT, const float* __restrict__ bias,
            int M, int N, int K) {
    __shared__ float sA[2][16][256];
    __shared__ float sB[2][16][128];
    int tid = threadIdx.x;
    int bm = blockIdx.y * 256;
    int bn = blockIdx.x * 128;
    int tm = (tid >> 4) * 16;
    int tn = tid & 15;

    float4 ra[4]; float4 rb[2];

    u64 acc[8][8];
    #pragma unroll
    for (int i = 0; i < 8; i++)
        #pragma unroll
        for (int s = 0; s < 8; s++) acc[i][s] = 0ull;

    #pragma unroll
    for (int i = 0; i < 4; i++) {
        int id = i * 256 + tid, r = id >> 2, kq = (id & 3) * 4;
        ra[i] = *(const float4*)(A + (size_t)(bm + r) * K + kq);
    }
    #pragma unroll
    for (int i = 0; i < 2; i++) {
        int id = i * 256 + tid, kk = id >> 5, nq = (id & 31) * 4;
        rb[i] = *(const float4*)(BT + (size_t)kk * N + bn + nq);
    }
    #pragma unroll
    for (int i = 0; i < 4; i++) {
        int id = i * 256 + tid, r = id >> 2, kq = (id & 3) * 4;
        sA[0][kq + 0][r] = ra[i].x; sA[0][kq + 1][r] = ra[i].y;
        sA[0][kq + 2][r] = ra[i].z; sA[0][kq + 3][r] = ra[i].w;
    }
    #pragma unroll
    for (int i = 0; i < 2; i++) {
        int id = i * 256 + tid, kk = id >> 5, nq = (id & 31) * 4;
        *(float4*)&sB[0][kk][nq] = rb[i];
    }
    __syncthreads();

    int nslab = K >> 4;
    for (int s = 0; s < nslab; s++) {
        int buf = s & 1;
        if (s + 1 < nslab) {
            int k0 = (s + 1) * 16;
            #pragma unroll
            for (int i = 0; i < 4; i++) {
                int id = i * 256 + tid, r = id >> 2, kq = (id & 3) * 4;
                ra[i] = *(const float4*)(A + (size_t)(bm + r) * K + k0 + kq);
            }
            #pragma unroll
            for (int i = 0; i < 2; i++) {
                int id = i * 256 + tid, kk = id >> 5, nq = (id & 31) * 4;
                rb[i] = *(const float4*)(BT + (size_t)(k0 + kk) * N + bn + nq);
            }
        }
        #pragma unroll
        for (int k = 0; k < 16; k++) {
            u64 a[8];
            *(ulonglong2*)&a[0] = *(const ulonglong2*)&sA[buf][k][tm];
            *(ulonglong2*)&a[2] = *(const ulonglong2*)&sA[buf][k][tm + 4];
            *(ulonglong2*)&a[4] = *(const ulonglong2*)&sA[buf][k][tm + 8];
            *(ulonglong2*)&a[6] = *(const ulonglong2*)&sA[buf][k][tm + 12];
            #pragma unroll
            for (int sn = 0; sn < 8; sn++) {
                unsigned bv = *(const unsigned*)&sB[buf][k][tn + 16 * sn];
                u64 b2 = dup2(bv);
                #pragma unroll
                for (int i = 0; i < 8; i++)
                    fma2(acc[i][sn], a[i], b2);
            }
        }
        if (s + 1 < nslab) {
            int nb = buf ^ 1;
            #pragma unroll
            for (int i = 0; i < 4; i++) {
                int id = i * 256 + tid, r = id >> 2, kq = (id & 3) * 4;
                sA[nb][kq + 0][r] = ra[i].x; sA[nb][kq + 1][r] = ra[i].y;
                sA[nb][kq + 2][r] = ra[i].z; sA[nb][kq + 3][r] = ra[i].w;
            }
            #pragma unroll
            for (int i = 0; i < 2; i++) {
                int id = i * 256 + tid, kk = id >> 5, nq = (id & 31) * 4;
                *(float4*)&sB[nb][kk][nq] = rb[i];
            }
            __syncthreads();
        }
    }
    #pragma unroll
    for (int i = 0; i < 8; i++) {
        size_t r0 = (size_t)(bm + tm + 2 * i) * N;
        size_t r1 = r0 + N;
        #pragma unroll
        for (int sn = 0; sn < 8; sn++) {
            int col = bn + tn + 16 * sn;
            float2 v = unpk(acc[i][sn]);
            float bv = bias ? bias[col] : 0.f;
            C[r0 + col] = v.x + bv;
            C[r1 + col] = v.y + bv;
        }
    }
}

// ---------------------------------------------------------------------------
// persistent GRU recurrence, dual-group interleaved software pipeline.
// 128 CTAs = 32 j-tiles x 4 pairs; CTA (p, jt) handles b-groups p and p+4
// (8 batches each). While group A's barrier propagates, group B computes.
// Weights register-resident (j-split), k-packed f32x2 dot products.
// ---------------------------------------------------------------------------
__global__ __launch_bounds__(256, 1)
void k_recur(const float* __restrict__ Gi, float* __restrict__ hist,
             const float* __restrict__ Whh, const float* __restrict__ bhh,
             const int* __restrict__ nsel) {
    extern __shared__ float sm[];
    float* sh  = sm;               // [8 b][512]
    float* red = sm + 8 * 512;     // [8 b][REDS]
    int tid = threadIdx.x;
    int jt = blockIdx.x & 31;
    int p  = blockIdx.x >> 5;      // 0..3
    int j0 = jt * 16;
    int bA0 = p * 8, bB0 = (p + 4) * 8;

    int jj = tid & 15;
    int kc = tid >> 4;             // 16 chunks of 32 k
    int k0 = kc * 32;
    int qx = (kc & 1) << 2;
    int wi = tid >> 5;
    int lane = tid & 31;
    int j2 = j0 + jj;
    int bb2 = tid >> 4;            // phase2: valid when tid < 128 (bb2 0..7)
    bool ph2 = tid < 128;
    int bA2 = bA0 + (bb2 & 7), bB2 = bB0 + (bb2 & 7);

    // weights -> registers (shared across both groups; j-dependent only)
    u64 w2[3][16];
    #pragma unroll
    for (int g = 0; g < 3; g++) {
        const float* wrow = Whh + (size_t)(g * 512 + j2) * 512;
        #pragma unroll
        for (int q = 0; q < 8; q++) {
            int keff = k0 + 4 * (q ^ qx);
            w2[g][2*q + 0] = *(const u64*)(wrow + keff);
            w2[g][2*q + 1] = *(const u64*)(wrow + keff + 2);
        }
    }
    float br = bhh[j2], bz = bhh[512 + j2], bn2 = bhh[1024 + j2];
    int limA = TT, limB = TT;
    if (nsel && ph2) { limA = nsel[bA2]; limB = nsel[bB2]; }
    unsigned* barA = &g_bars[p * 32];
    unsigned* barB = &g_bars[(p + 4) * 32];

    for (int t = 0; t < TT; t++) {
        // prefetch Gi for both groups (independent of barriers)
        float girA=0.f, gizA=0.f, ginA=0.f, girB=0.f, gizB=0.f, ginB=0.f;
        if (ph2) {
            const float* ga = Gi + ((size_t)bA2 * TT + t) * G3;
            girA = __ldcg(ga + j2); gizA = __ldcg(ga + 512 + j2);
            ginA = __ldcg(ga + 1024 + j2);
            const float* gb = Gi + ((size_t)bB2 * TT + t) * G3;
            girB = __ldcg(gb + j2); gizB = __ldcg(gb + 512 + j2);
            ginB = __ldcg(gb + 1024 + j2);
        }
        const float* hsrc = g_h[t & 1];
        float* hdst = g_h[(t + 1) & 1];

        #pragma unroll
        for (int grp = 0; grp < 2; grp++) {
            int b0   = grp ? bB0 : bA0;
            unsigned* bar = grp ? barB : barA;
            // wait for all 32 CTAs of this group to have posted step t-1
            if (t > 0) {
                if (tid == 0) {
                    unsigned tgt = 32u * (unsigned)t;
                    while (ld_acq(bar) < tgt) { }
                }
                __syncthreads();
            }
            // stage h tile (8 b x 512) into smem, bypassing L1
            #pragma unroll
            for (int i = 0; i < 4; i++) {
                int id = tid + i * 256;        // 0..1023 float4 slots
                int lb = id >> 7;              // 0..7
                int lk = (id & 127) * 4;
                float4 v = __ldcg((const float4*)(hsrc + (size_t)(b0 + lb) * HH + lk));
                *(float4*)&sh[lb * 512 + lk] = v;
            }
            __syncthreads();

            // phase1: partial dots over this thread's 32-k chunk, 8 b
            #pragma unroll 1
            for (int b = 0; b < 8; b++) {
                const ulonglong2* hp = (const ulonglong2*)&sh[b * 512 + k0];
                u64 a0 = 0ull, a1 = 0ull, a2 = 0ull;
                #pragma unroll
                for (int q = 0; q < 8; q++) {
                    ulonglong2 hv = hp[q ^ qx];
                    fma2(a0, hv.x, w2[0][2*q]); fma2(a0, hv.y, w2[0][2*q + 1]);
                    fma2(a1, hv.x, w2[1][2*q]); fma2(a1, hv.y, w2[1][2*q + 1]);
                    fma2(a2, hv.x, w2[2][2*q]); fma2(a2, hv.y, w2[2][2*q + 1]);
                }
                a0 = add2(a0, shx16(a0));
                a1 = add2(a1, shx16(a1));
                a2 = add2(a2, shx16(a2));
                if (lane < 16) {
                    float2 f0 = unpk(a0), f1 = unpk(a1), f2 = unpk(a2);
                    int base = b * REDS + wi * 48 + jj;
                    red[base]      = f0.x + f0.y;
                    red[base + 16] = f1.x + f1.y;
                    red[base + 32] = f2.x + f2.y;
                }
            }
            __syncthreads();

            // phase2: gates for (b, j2) by the first 128 threads
            if (ph2) {
                float sr = br, sz = bz, sn = bn2;
                #pragma unroll
                for (int w = 0; w < 8; w++) {
                    int base = bb2 * REDS + w * 48 + jj;
                    sr += red[base];
                    sz += red[base + 16];
                    sn += red[base + 32];
                }
                float gir = grp ? girB : girA;
                float giz = grp ? gizB : gizA;
                float gin = grp ? ginB : ginA;
                int   lim = grp ? limB : limA;
                int   b2  = grp ? bB2  : bA2;
                float r = 1.f / (1.f + expf(-(gir + sr)));
                float z = 1.f / (1.f + expf(-(giz + sz)));
                float n = tanhf(gin + r * sn);
                float hold = sh[bb2 * 512 + j2];
                float hn = (1.f - z) * n + z * hold;
                bool valid = t < lim;
                hdst[b2 * HH + j2] = valid ? hn : hold;
                hist[((size_t)b2 * TT + t) * HH + j2] = valid ? hn : 0.f;
            }
            __syncthreads();
            if (tid == 0) red_rel(bar);   // release: covers all threads' stores
        }
    }
}

// ---------------------------------------------------------------------------
__global__ void k_selargmax(const float* __restrict__ hist,
                            const float* __restrict__ Ws,
                            const float* __restrict__ bs) {
    int gw = (blockIdx.x * blockDim.x + threadIdx.x) >> 5;
    int lane = threadIdx.x & 31;
    if (gw >= BB * TT) return;
    const float* h = hist + (size_t)gw * HH;
    float l0 = 0.f, l1 = 0.f;
    #pragma unroll 4
    for (int jv = lane; jv < HH; jv += 32) {
        float hv = h[jv];
        l0 += hv * Ws[jv];
        l1 += hv * Ws[HH + jv];
    }
    #pragma unroll
    for (int o = 16; o; o >>= 1) {
        l0 += __shfl_down_sync(0xffffffffu, l0, o);
        l1 += __shfl_down_sync(0xffffffffu, l1, o);
    }
    if (lane == 0)
        g_sel[gw] = ((l1 + bs[1]) > (l0 + bs[0])) ? 1 : 0;
}

// ---------------------------------------------------------------------------
__global__ void k_fix(const int* __restrict__ mask) {
    int b = blockIdx.x;
    int lane = threadIdx.x;
    int len = 0;
    for (int t = lane; t < TT; t += 32) len += mask[b * TT + t];
    #pragma unroll
    for (int o = 16; o; o >>= 1) len += __shfl_down_sync(0xffffffffu, len, o);
    len = __shfl_sync(0xffffffffu, len, 0);
    int cnt = 0;
    for (int c = 0; c < TT; c += 32) {
        int t = c + lane;
        int s = g_sel[b * TT + t];
        if (t == 0) s = 1;
        if (t == len - 1) s = 1;
        if (t >= len) s = 0;
        unsigned bal = __ballot_sync(0xffffffffu, s);
        int pre = __popc(bal & ((1u << lane) - 1u));
        if (s) g_order[b * TT + cnt + pre] = t;
        cnt += __popc(bal);
    }
    if (lane == 0) g_nsel[b] = cnt;
}

// ---------------------------------------------------------------------------
__global__ void k_gather(const float* __restrict__ emb, float* __restrict__ dst) {
    int row = blockIdx.x;               // b*T + p
    int b = row >> 9, p = row & 511;
    float4 v = make_float4(0.f, 0.f, 0.f, 0.f);
    if (p < g_nsel[b]) {
        int t = g_order[row];
        v = ((const float4*)(emb + ((size_t)b * TT + t) * EE))[threadIdx.x];
    }
    ((float4*)(dst + (size_t)row * EE))[threadIdx.x] = v;
}

// ---------------------------------------------------------------------------
__global__ void k_pool(const float* __restrict__ U, const float* __restrict__ bc,
                       int kw, int Nn, int seg) {
    int b = blockIdx.x;
    int f = threadIdx.x;
    int tlim = TT - kw + 1;
    int t0 = blockIdx.y * 64;
    int t1 = t0 + 64 < tlim ? t0 + 64 : tlim;
    float bcv = bc[f];
    float m = 0.f;
    const float* Ub = U + (size_t)b * TT * Nn + (size_t)f * kw;
    for (int t = t0; t < t1; t++) {
        float s = bcv;
        #pragma unroll 5
        for (int dt = 0; dt < kw; dt++)
            s += Ub[(size_t)(t + dt) * Nn + dt];
        m = fmaxf(m, fmaxf(s, 0.f));
    }
    atomicMax((int*)&g_pooled[b * (3 * NF) + seg + f], __float_as_int(m));
}

// ---------------------------------------------------------------------------
__global__ void k_final(const float* __restrict__ Wo, const float* __restrict__ bo,
                        float* __restrict__ out) {
    __shared__ float redf[256];
    int b = blockIdx.x, tid = threadIdx.x;
    float s = 0.f;
    for (int f = tid; f < 3 * NF; f += 256)
        s += g_pooled[b * (3 * NF) + f] * Wo[f];
    redf[tid] = s;
    __syncthreads();
    for (int o = 128; o; o >>= 1) {
        if (tid < o) redf[tid] += redf[tid + o];
        __syncthreads();
    }
    if (tid == 0) out[b] = redf[0] + bo[0];
}

// ---------------------------------------------------------------------------
extern "C" void kernel_launch(void* const* d_in, const int* in_sizes, int n_in,
                              void* d_out, int out_size) {
    const float* emb   = (const float*)d_in[0];
    const int*   mask  = (const int*)  d_in[1];
    const float* Wih_c = (const float*)d_in[2];
    const float* Whh_c = (const float*)d_in[3];
    const float* bih_c = (const float*)d_in[4];
    const float* bhh_c = (const float*)d_in[5];
    const float* Ws    = (const float*)d_in[6];
    const float* bs    = (const float*)d_in[7];
    const float* Wih0  = (const float*)d_in[8];
    const float* Whh0  = (const float*)d_in[9];
    const float* bih0  = (const float*)d_in[10];
    const float* bhh0  = (const float*)d_in[11];
    const float* Wih1  = (const float*)d_in[12];
    const float* Whh1  = (const float*)d_in[13];
    const float* bih1  = (const float*)d_in[14];
    const float* bhh1  = (const float*)d_in[15];
    const float* Wc3   = (const float*)d_in[16];
    const float* bc3   = (const float*)d_in[17];
    const float* Wc4   = (const float*)d_in[18];
    const float* bc4   = (const float*)d_in[19];
    const float* Wc5   = (const float*)d_in[20];
    const float* bc5   = (const float*)d_in[21];
    const float* Wo    = (const float*)d_in[22];
    const float* bo    = (const float*)d_in[23];
    float* out = (float*)d_out;

    cudaFuncSetAttribute(k_recur, cudaFuncAttributeMaxDynamicSharedMemorySize,
                         RSM_BYTES);

    float *pGi, *pS0, *pS1, *pNe, *pU, *pWT;
    int* pNsel;
    cudaGetSymbolAddress((void**)&pGi,   g_Gi);
    cudaGetSymbolAddress((void**)&pS0,   g_seq0);
    cudaGetSymbolAddress((void**)&pS1,   g_seq1);
    cudaGetSymbolAddress((void**)&pNe,   g_newemb);
    cudaGetSymbolAddress((void**)&pU,    g_U);
    cudaGetSymbolAddress((void**)&pWT,   g_WT);
    cudaGetSymbolAddress((void**)&pNsel, g_nsel);

    dim3 t32x8(32, 8);

    // ---- selector GRU ----
    k_transpose<<<dim3(EE/32, G3/32), t32x8>>>(pWT, Wih_c, G3, EE);
    k_gemm<<<dim3(G3/128, MALL/256), 256>>>(pGi, emb, pWT, bih_c, MALL, G3, EE);
    k_reset<<<256, 256>>>();
    k_recur<<<NBLK, 256, RSM_BYTES>>>(pGi, pS0, Whh_c, bhh_c, nullptr);
    k_selargmax<<<(BB*TT*32 + 255)/256, 256>>>(pS0, Ws, bs);
    k_fix<<<BB, 32>>>(mask);
    k_gather<<<MALL, EE/4>>>(emb, pNe);

    // ---- layer 0 ----
    k_transpose<<<dim3(EE/32, G3/32), t32x8>>>(pWT, Wih0, G3, EE);
    k_gemm<<<dim3(G3/128, MALL/256), 256>>>(pGi, pNe, pWT, bih0, MALL, G3, EE);
    k_reset<<<256, 256>>>();
    k_recur<<<NBLK, 256, RSM_BYTES>>>(pGi, pS1, Whh0, bhh0, pNsel);

    // ---- layer 1 ----
    k_transpose<<<dim3(HH/32, G3/32), t32x8>>>(pWT, Wih1, G3, HH);
    k_gemm<<<dim3(G3/128, MALL/256), 256>>>(pGi, pS1, pWT, bih1, MALL, G3, HH);
    k_reset<<<256, 256>>>();
    k_recur<<<NBLK, 256, RSM_BYTES>>>(pGi, pS0, Whh1, bhh1, pNsel);

    // ---- convs (GEMM + pool), kw = 3,4,5 ----
    k_zero_pooled<<<(BB*3*NF + 255)/256, 256>>>();

    k_transpose<<<dim3(HH/32, (NF*3)/32), t32x8>>>(pWT, Wc3, NF*3, HH);
    k_gemm<<<dim3((NF*3)/128, MALL/256), 256>>>(pU, pS0, pWT, nullptr, MALL, NF*3, HH);
    k_pool<<<dim3(BB, 8), NF>>>(pU, bc3, 3, NF*3, 0);

    k_transpose<<<dim3(HH/32, (NF*4)/32), t32x8>>>(pWT, Wc4, NF*4, HH);
    k_gemm<<<dim3((NF*4)/128, MALL/256), 256>>>(pU, pS0, pWT, nullptr, MALL, NF*4, HH);
    k_pool<<<dim3(BB, 8), NF>>>(pU, bc4, 4, NF*4, NF);

    k_transpose<<<dim3(HH/32, (NF*5)/32), t32x8>>>(pWT, Wc5, NF*5, HH);
    k_gemm<<<dim3((NF*5)/128, MALL/256), 256>>>(pU, pS0, pWT, nullptr, MALL, NF*5, HH);
    k_pool<<<dim3(BB, 8), NF>>>(pU, bc5, 5, NF*5, 2*NF);

    // ---- final projection ----
    k_final<<<BB, 256>>>(Wo, bo, out);
}

// round 6
// speedup vs baseline: 1.2202x; 1.2202x over previous
#include <cuda_runtime.h>
#include <math.h>
#include <stdint.h>
#include <stddef.h>

typedef unsigned long long u64;

// Problem dims
#define BB    64
#define TT    512
#define EE    768
#define HH    512
#define G3    1536
#define NF    256
#define MALL  (BB*TT)          // 32768

// -------- recurrence persistent-kernel config --------
#define NBLK      128          // co-resident worker CTAs
#define REDS      392          // red stride (mod 32 != 0 -> conflict-free)
#define RSM_FLOATS (16*512 + 16*REDS)
#define RSM_BYTES  (RSM_FLOATS*4)   // 57344 B

// ----------------- device scratch (statics; no cudaMalloc allowed) ----------
__device__ float g_Gi[(size_t)MALL * G3];      // reused per GRU pass
__device__ float g_seq0[(size_t)MALL * HH];    // selector hist, later out1
__device__ float g_seq1[(size_t)MALL * HH];    // out0
__device__ float g_newemb[(size_t)MALL * EE];
__device__ float g_U[(size_t)MALL * (NF*5)];   // conv GEMM out (reused)
__device__ float g_WT[G3 * EE];                // transposed weights scratch
__device__ float g_h[2][BB * HH];              // hidden-state ping-pong
__device__ int   g_sel[BB * TT];
__device__ int   g_order[BB * TT];
__device__ int   g_nsel[BB];
__device__ float g_pooled[BB * 3 * NF];
__device__ unsigned g_bar4[4 * 32];            // per-b-tile barrier counters

// ----------------------------- f32x2 helpers --------------------------------
__device__ __forceinline__ void fma2(u64& d, u64 a, u64 b) {
    asm("fma.rn.f32x2 %0,%1,%2,%0;" : "+l"(d) : "l"(a), "l"(b));
}
__device__ __forceinline__ u64 add2(u64 a, u64 b) {
    u64 r; asm("add.rn.f32x2 %0,%1,%2;" : "=l"(r) : "l"(a), "l"(b)); return r;
}
__device__ __forceinline__ float2 unpk(u64 v) {
    float2 r; asm("mov.b64 {%0,%1},%2;" : "=f"(r.x), "=f"(r.y) : "l"(v)); return r;
}
__device__ __forceinline__ u64 dup2(unsigned v) {
    u64 r; asm("mov.b64 %0,{%1,%1};" : "=l"(r) : "r"(v)); return r;
}
__device__ __forceinline__ u64 shx16(u64 v) {
    unsigned lo = (unsigned)v, hi = (unsigned)(v >> 32);
    lo = __shfl_xor_sync(0xffffffffu, lo, 16);
    hi = __shfl_xor_sync(0xffffffffu, hi, 16);
    return ((u64)hi << 32) | (u64)lo;
}
// release/acquire barrier primitives
__device__ __forceinline__ unsigned ld_acq(const unsigned* p) {
    unsigned v;
    asm volatile("ld.acquire.gpu.global.u32 %0,[%1];" : "=r"(v) : "l"(p));
    return v;
}
__device__ __forceinline__ void red_rel(unsigned* p) {
    asm volatile("red.release.gpu.global.add.u32 [%0],1;" :: "l"(p));
}

// ---------------------------------------------------------------------------
__global__ void k_reset() {
    int i = blockIdx.x * blockDim.x + threadIdx.x;
    if (i < 4 * 32) g_bar4[i] = 0u;
    if (i < 2 * BB * HH) ((float*)g_h)[i] = 0.f;
}
__global__ void k_zero_pooled() {
    int i = blockIdx.x * blockDim.x + threadIdx.x;
    if (i < BB * 3 * NF) g_pooled[i] = 0.f;
}

// ---------------------------------------------------------------------------
// generic transpose: dst[C][R] = src[R][C]   (R, C multiples of 32)
// ---------------------------------------------------------------------------
__global__ void k_transpose(float* dst, const float* src, int R, int C) {
    __shared__ float tile[32][33];
    int c0 = blockIdx.x * 32, r0 = blockIdx.y * 32;
    int tx = threadIdx.x, ty = threadIdx.y;
    #pragma unroll
    for (int i = 0; i < 32; i += 8)
        tile[ty + i][tx] = src[(size_t)(r0 + ty + i) * C + c0 + tx];
    __syncthreads();
    #pragma unroll
    for (int i = 0; i < 32; i += 8)
        dst[(size_t)(c0 + ty + i) * R + r0 + tx] = tile[tx][ty + i];
}

// ---------------------------------------------------------------------------
// GEMM (f32x2): C[M][N] = A[M][K] @ BT[K][N] (+ bias[n]).
// 256x128 tile, 16-k slab, 256 threads, double-buffered smem.
// mode 0: always compute. mode 1: if tile's rows are all >= nsel[b], skip
// entirely (consumer masks). mode 2: same condition, write zeros.
// Tiles are 256 rows => each tile lies inside one batch (512 rows/batch).
// ---------------------------------------------------------------------------
__global__ __launch_bounds__(256, 1)
void k_gemm(float* __restrict__ C, const float* __restrict__ A,
            const float* __restrict__ BT, const float* __restrict__ bias,
            int M, int N, int K, const int* __restrict__ nsel, int mode) {
    __shared__ float sA[2][16][256];
    __shared__ float sB[2][16][128];
    int tid = threadIdx.x;
    int bm = blockIdx.y * 256;
    int bn = blockIdx.x * 128;

    if (mode != 0) {
        int p0 = bm & 511;
        if (p0 >= nsel[bm >> 9]) {          // whole tile is zero-input
            if (mode == 2) {
                float4 z = make_float4(0.f, 0.f, 0.f, 0.f);
                for (int i = tid; i < 256 * 32; i += 256) {
                    int row = i >> 5, c4 = (i & 31) * 4;
                    *(float4*)(C + (size_t)(bm + row) * N + bn + c4) = z;
                }
            }
            return;
        }
    }

    int tm = (tid >> 4) * 16;
    int tn = tid & 15;

    float4 ra[4]; float4 rb[2];

    u64 acc[8][8];
    #pragma unroll
    for (int i = 0; i < 8; i++)
        #pragma unroll
        for (int s = 0; s < 8; s++) acc[i][s] = 0ull;

    #pragma unroll
    for (int i = 0; i < 4; i++) {
        int id = i * 256 + tid, r = id >> 2, kq = (id & 3) * 4;
        ra[i] = *(const float4*)(A + (size_t)(bm + r) * K + kq);
    }
    #pragma unroll
    for (int i = 0; i < 2; i++) {
        int id = i * 256 + tid, kk = id >> 5, nq = (id & 31) * 4;
        rb[i] = *(const float4*)(BT + (size_t)kk * N + bn + nq);
    }
    #pragma unroll
    for (int i = 0; i < 4; i++) {
        int id = i * 256 + tid, r = id >> 2, kq = (id & 3) * 4;
        sA[0][kq + 0][r] = ra[i].x; sA[0][kq + 1][r] = ra[i].y;
        sA[0][kq + 2][r] = ra[i].z; sA[0][kq + 3][r] = ra[i].w;
    }
    #pragma unroll
    for (int i = 0; i < 2; i++) {
        int id = i * 256 + tid, kk = id >> 5, nq = (id & 31) * 4;
        *(float4*)&sB[0][kk][nq] = rb[i];
    }
    __syncthreads();

    int nslab = K >> 4;
    for (int s = 0; s < nslab; s++) {
        int buf = s & 1;
        if (s + 1 < nslab) {
            int k0 = (s + 1) * 16;
            #pragma unroll
            for (int i = 0; i < 4; i++) {
                int id = i * 256 + tid, r = id >> 2, kq = (id & 3) * 4;
                ra[i] = *(const float4*)(A + (size_t)(bm + r) * K + k0 + kq);
            }
            #pragma unroll
            for (int i = 0; i < 2; i++) {
                int id = i * 256 + tid, kk = id >> 5, nq = (id & 31) * 4;
                rb[i] = *(const float4*)(BT + (size_t)(k0 + kk) * N + bn + nq);
            }
        }
        #pragma unroll
        for (int k = 0; k < 16; k++) {
            u64 a[8];
            *(ulonglong2*)&a[0] = *(const ulonglong2*)&sA[buf][k][tm];
            *(ulonglong2*)&a[2] = *(const ulonglong2*)&sA[buf][k][tm + 4];
            *(ulonglong2*)&a[4] = *(const ulonglong2*)&sA[buf][k][tm + 8];
            *(ulonglong2*)&a[6] = *(const ulonglong2*)&sA[buf][k][tm + 12];
            #pragma unroll
            for (int sn = 0; sn < 8; sn++) {
                unsigned bv = *(const unsigned*)&sB[buf][k][tn + 16 * sn];
                u64 b2 = dup2(bv);
                #pragma unroll
                for (int i = 0; i < 8; i++)
                    fma2(acc[i][sn], a[i], b2);
            }
        }
        if (s + 1 < nslab) {
            int nb = buf ^ 1;
            #pragma unroll
            for (int i = 0; i < 4; i++) {
                int id = i * 256 + tid, r = id >> 2, kq = (id & 3) * 4;
                sA[nb][kq + 0][r] = ra[i].x; sA[nb][kq + 1][r] = ra[i].y;
                sA[nb][kq + 2][r] = ra[i].z; sA[nb][kq + 3][r] = ra[i].w;
            }
            #pragma unroll
            for (int i = 0; i < 2; i++) {
                int id = i * 256 + tid, kk = id >> 5, nq = (id & 31) * 4;
                *(float4*)&sB[nb][kk][nq] = rb[i];
            }
            __syncthreads();
        }
    }
    #pragma unroll
    for (int i = 0; i < 8; i++) {
        size_t r0 = (size_t)(bm + tm + 2 * i) * N;
        size_t r1 = r0 + N;
        #pragma unroll
        for (int sn = 0; sn < 8; sn++) {
            int col = bn + tn + 16 * sn;
            float2 v = unpk(acc[i][sn]);
            float bv = bias ? bias[col] : 0.f;
            C[r0 + col] = v.x + bv;
            C[r1 + col] = v.y + bv;
        }
    }
}

// ---------------------------------------------------------------------------
// persistent GRU recurrence (R3 structure, release/acquire barrier).
// grid = 128 CTAs (4 b-tiles x 32 j-tiles), 256 threads.
// ---------------------------------------------------------------------------
__global__ __launch_bounds__(256, 1)
void k_recur(const float* __restrict__ Gi, float* __restrict__ hist,
             const float* __restrict__ Whh, const float* __restrict__ bhh,
             const int* __restrict__ nsel) {
    extern __shared__ float sm[];
    float* sh  = sm;               // [16 b][512]
    float* red = sm + 16 * 512;    // [16 b][REDS]: 8 warp x 3 gate x 16 jj
    int tid = threadIdx.x;
    int bt = blockIdx.x & 3, jt = blockIdx.x >> 2;
    int b0 = bt * 16, j0 = jt * 16;

    int jj = tid & 15;
    int kc = tid >> 4;             // 16 chunks of 32 k
    int k0 = kc * 32;
    int qx = (kc & 1) << 2;        // bank-conflict-avoiding permutation
    int wi = tid >> 5;
    int lane = tid & 31;
    int bb2 = tid >> 4;
    int j2 = j0 + jj;
    int b2 = b0 + bb2;

    // weights -> registers, ordered to match permuted h-read sequence
    u64 w2[3][16];
    #pragma unroll
    for (int g = 0; g < 3; g++) {
        const float* wrow = Whh + (size_t)(g * 512 + j0 + jj) * 512;
        #pragma unroll
        for (int q = 0; q < 8; q++) {
            int keff = k0 + 4 * (q ^ qx);
            w2[g][2*q + 0] = *(const u64*)(wrow + keff);
            w2[g][2*q + 1] = *(const u64*)(wrow + keff + 2);
        }
    }
    float br = bhh[j2], bz = bhh[512 + j2], bn2 = bhh[1024 + j2];
    int lim = nsel ? nsel[b2] : TT;
    unsigned* barp = &g_bar4[bt * 32];

    for (int t = 0; t < TT; t++) {
        // prefetch Gi (independent of barrier; hides LDG behind poll)
        const float* gp = Gi + ((size_t)b2 * TT + t) * G3;
        float gir = __ldcg(gp + j2);
        float giz = __ldcg(gp + 512 + j2);
        float gin = __ldcg(gp + 1024 + j2);

        // wait for all 32 CTAs of this b-tile to have posted step t-1
        if (t > 0) {
            if (tid == 0) {
                unsigned tgt = 32u * (unsigned)t;
                while (ld_acq(barp) < tgt) { }
            }
            __syncthreads();
        }

        const float* hsrc = g_h[t & 1];
        #pragma unroll
        for (int i = 0; i < 8; i++) {
            int id = tid + i * 256;
            int lb = id >> 7;
            int lk = (id & 127) * 4;
            float4 v = __ldcg((const float4*)(hsrc + (size_t)(b0 + lb) * HH + lk));
            *(float4*)&sh[lb * 512 + lk] = v;
        }
        __syncthreads();

        // phase1: partial dots over this thread's 32-k chunk, all 16 b
        #pragma unroll 1
        for (int b = 0; b < 16; b++) {
            const ulonglong2* hp = (const ulonglong2*)&sh[b * 512 + k0];
            u64 a0 = 0ull, a1 = 0ull, a2 = 0ull;
            #pragma unroll
            for (int q = 0; q < 8; q++) {
                ulonglong2 hv = hp[q ^ qx];
                fma2(a0, hv.x, w2[0][2*q]); fma2(a0, hv.y, w2[0][2*q + 1]);
                fma2(a1, hv.x, w2[1][2*q]); fma2(a1, hv.y, w2[1][2*q + 1]);
                fma2(a2, hv.x, w2[2][2*q]); fma2(a2, hv.y, w2[2][2*q + 1]);
            }
            a0 = add2(a0, shx16(a0));
            a1 = add2(a1, shx16(a1));
            a2 = add2(a2, shx16(a2));
            if (lane < 16) {
                float2 f0 = unpk(a0), f1 = unpk(a1), f2 = unpk(a2);
                int base = b * REDS + wi * 48 + jj;
                red[base]      = f0.x + f0.y;
                red[base + 16] = f1.x + f1.y;
                red[base + 32] = f2.x + f2.y;
            }
        }
        __syncthreads();

        // phase2: gates for (b2, j2)
        float sr = br, sz = bz, sn = bn2;
        #pragma unroll
        for (int w = 0; w < 8; w++) {
            int base = bb2 * REDS + w * 48 + jj;
            sr += red[base];
            sz += red[base + 16];
            sn += red[base + 32];
        }
        float r = 1.f / (1.f + expf(-(gir + sr)));
        float z = 1.f / (1.f + expf(-(giz + sz)));
        float n = tanhf(gin + r * sn);
        float hold = sh[bb2 * 512 + j2];
        float hn = (1.f - z) * n + z * hold;
        bool valid = t < lim;
        g_h[(t + 1) & 1][b2 * HH + j2] = valid ? hn : hold;
        hist[((size_t)b2 * TT + t) * HH + j2] = valid ? hn : 0.f;

        __syncthreads();
        if (tid == 0) red_rel(barp);   // release: covers all threads' stores
    }
}

// ---------------------------------------------------------------------------
__global__ void k_selargmax(const float* __restrict__ hist,
                            const float* __restrict__ Ws,
                            const float* __restrict__ bs) {
    int gw = (blockIdx.x * blockDim.x + threadIdx.x) >> 5;
    int lane = threadIdx.x & 31;
    if (gw >= BB * TT) return;
    const float* h = hist + (size_t)gw * HH;
    float l0 = 0.f, l1 = 0.f;
    #pragma unroll 4
    for (int jv = lane; jv < HH; jv += 32) {
        float hv = h[jv];
        l0 += hv * Ws[jv];
        l1 += hv * Ws[HH + jv];
    }
    #pragma unroll
    for (int o = 16; o; o >>= 1) {
        l0 += __shfl_down_sync(0xffffffffu, l0, o);
        l1 += __shfl_down_sync(0xffffffffu, l1, o);
    }
    if (lane == 0)
        g_sel[gw] = ((l1 + bs[1]) > (l0 + bs[0])) ? 1 : 0;
}

// ---------------------------------------------------------------------------
__global__ void k_fix(const int* __restrict__ mask) {
    int b = blockIdx.x;
    int lane = threadIdx.x;
    int len = 0;
    for (int t = lane; t < TT; t += 32) len += mask[b * TT + t];
    #pragma unroll
    for (int o = 16; o; o >>= 1) len += __shfl_down_sync(0xffffffffu, len, o);
    len = __shfl_sync(0xffffffffu, len, 0);
    int cnt = 0;
    for (int c = 0; c < TT; c += 32) {
        int t = c + lane;
        int s = g_sel[b * TT + t];
        if (t == 0) s = 1;
        if (t == len - 1) s = 1;
        if (t >= len) s = 0;
        unsigned bal = __ballot_sync(0xffffffffu, s);
        int pre = __popc(bal & ((1u << lane) - 1u));
        if (s) g_order[b * TT + cnt + pre] = t;
        cnt += __popc(bal);
    }
    if (lane == 0) g_nsel[b] = cnt;
}

// ---------------------------------------------------------------------------
__global__ void k_gather(const float* __restrict__ emb, float* __restrict__ dst) {
    int row = blockIdx.x;               // b*T + p
    int b = row >> 9, p = row & 511;
    float4 v = make_float4(0.f, 0.f, 0.f, 0.f);
    if (p < g_nsel[b]) {
        int t = g_order[row];
        v = ((const float4*)(emb + ((size_t)b * TT + t) * EE))[threadIdx.x];
    }
    ((float4*)(dst + (size_t)row * EE))[threadIdx.x] = v;
}

// ---------------------------------------------------------------------------
__global__ void k_pool(const float* __restrict__ U, const float* __restrict__ bc,
                       int kw, int Nn, int seg) {
    int b = blockIdx.x;
    int f = threadIdx.x;
    int tlim = TT - kw + 1;
    int t0 = blockIdx.y * 64;
    int t1 = t0 + 64 < tlim ? t0 + 64 : tlim;
    float bcv = bc[f];
    float m = 0.f;
    const float* Ub = U + (size_t)b * TT * Nn + (size_t)f * kw;
    for (int t = t0; t < t1; t++) {
        float s = bcv;
        #pragma unroll 5
        for (int dt = 0; dt < kw; dt++)
            s += Ub[(size_t)(t + dt) * Nn + dt];
        m = fmaxf(m, fmaxf(s, 0.f));
    }
    atomicMax((int*)&g_pooled[b * (3 * NF) + seg + f], __float_as_int(m));
}

// ---------------------------------------------------------------------------
__global__ void k_final(const float* __restrict__ Wo, const float* __restrict__ bo,
                        float* __restrict__ out) {
    __shared__ float redf[256];
    int b = blockIdx.x, tid = threadIdx.x;
    float s = 0.f;
    for (int f = tid; f < 3 * NF; f += 256)
        s += g_pooled[b * (3 * NF) + f] * Wo[f];
    redf[tid] = s;
    __syncthreads();
    for (int o = 128; o; o >>= 1) {
        if (tid < o) redf[tid] += redf[tid + o];
        __syncthreads();
    }
    if (tid == 0) out[b] = redf[0] + bo[0];
}

// ---------------------------------------------------------------------------
extern "C" void kernel_launch(void* const* d_in, const int* in_sizes, int n_in,
                              void* d_out, int out_size) {
    const float* emb   = (const float*)d_in[0];
    const int*   mask  = (const int*)  d_in[1];
    const float* Wih_c = (const float*)d_in[2];
    const float* Whh_c = (const float*)d_in[3];
    const float* bih_c = (const float*)d_in[4];
    const float* bhh_c = (const float*)d_in[5];
    const float* Ws    = (const float*)d_in[6];
    const float* bs    = (const float*)d_in[7];
    const float* Wih0  = (const float*)d_in[8];
    const float* Whh0  = (const float*)d_in[9];
    const float* bih0  = (const float*)d_in[10];
    const float* bhh0  = (const float*)d_in[11];
    const float* Wih1  = (const float*)d_in[12];
    const float* Whh1  = (const float*)d_in[13];
    const float* bih1  = (const float*)d_in[14];
    const float* bhh1  = (const float*)d_in[15];
    const float* Wc3   = (const float*)d_in[16];
    const float* bc3   = (const float*)d_in[17];
    const float* Wc4   = (const float*)d_in[18];
    const float* bc4   = (const float*)d_in[19];
    const float* Wc5   = (const float*)d_in[20];
    const float* bc5   = (const float*)d_in[21];
    const float* Wo    = (const float*)d_in[22];
    const float* bo    = (const float*)d_in[23];
    float* out = (float*)d_out;

    cudaFuncSetAttribute(k_recur, cudaFuncAttributeMaxDynamicSharedMemorySize,
                         RSM_BYTES);

    float *pGi, *pS0, *pS1, *pNe, *pU, *pWT;
    int* pNsel;
    cudaGetSymbolAddress((void**)&pGi,   g_Gi);
    cudaGetSymbolAddress((void**)&pS0,   g_seq0);
    cudaGetSymbolAddress((void**)&pS1,   g_seq1);
    cudaGetSymbolAddress((void**)&pNe,   g_newemb);
    cudaGetSymbolAddress((void**)&pU,    g_U);
    cudaGetSymbolAddress((void**)&pWT,   g_WT);
    cudaGetSymbolAddress((void**)&pNsel, g_nsel);

    dim3 t32x8(32, 8);

    // ---- selector GRU (exact fp32, full tiles) ----
    k_transpose<<<dim3(EE/32, G3/32), t32x8>>>(pWT, Wih_c, G3, EE);
    k_gemm<<<dim3(G3/128, MALL/256), 256>>>(pGi, emb, pWT, bih_c, MALL, G3, EE,
                                            nullptr, 0);
    k_reset<<<256, 256>>>();
    k_recur<<<NBLK, 256, RSM_BYTES>>>(pGi, pS0, Whh_c, bhh_c, nullptr);
    k_selargmax<<<(BB*TT*32 + 255)/256, 256>>>(pS0, Ws, bs);
    k_fix<<<BB, 32>>>(mask);
    k_gather<<<MALL, EE/4>>>(emb, pNe);

    // ---- layer 0 (skip all-invalid tiles, no write) ----
    k_transpose<<<dim3(EE/32, G3/32), t32x8>>>(pWT, Wih0, G3, EE);
    k_gemm<<<dim3(G3/128, MALL/256), 256>>>(pGi, pNe, pWT, bih0, MALL, G3, EE,
                                            pNsel, 1);
    k_reset<<<256, 256>>>();
    k_recur<<<NBLK, 256, RSM_BYTES>>>(pGi, pS1, Whh0, bhh0, pNsel);

    // ---- layer 1 ----
    k_transpose<<<dim3(HH/32, G3/32), t32x8>>>(pWT, Wih1, G3, HH);
    k_gemm<<<dim3(G3/128, MALL/256), 256>>>(pGi, pS1, pWT, bih1, MALL, G3, HH,
                                            pNsel, 1);
    k_reset<<<256, 256>>>();
    k_recur<<<NBLK, 256, RSM_BYTES>>>(pGi, pS0, Whh1, bhh1, pNsel);

    // ---- convs (GEMM + pool), kw = 3,4,5 (skip tiles -> zeros) ----
    k_zero_pooled<<<(BB*3*NF + 255)/256, 256>>>();

    k_transpose<<<dim3(HH/32, (NF*3)/32), t32x8>>>(pWT, Wc3, NF*3, HH);
    k_gemm<<<dim3((NF*3)/128, MALL/256), 256>>>(pU, pS0, pWT, nullptr, MALL,
                                                NF*3, HH, pNsel, 2);
    k_pool<<<dim3(BB, 8), NF>>>(pU, bc3, 3, NF*3, 0);

    k_transpose<<<dim3(HH/32, (NF*4)/32), t32x8>>>(pWT, Wc4, NF*4, HH);
    k_gemm<<<dim3((NF*4)/128, MALL/256), 256>>>(pU, pS0, pWT, nullptr, MALL,
                                                NF*4, HH, pNsel, 2);
    k_pool<<<dim3(BB, 8), NF>>>(pU, bc4, 4, NF*4, NF);

    k_transpose<<<dim3(HH/32, (NF*5)/32), t32x8>>>(pWT, Wc5, NF*5, HH);
    k_gemm<<<dim3((NF*5)/128, MALL/256), 256>>>(pU, pS0, pWT, nullptr, MALL,
                                                NF*5, HH, pNsel, 2);
    k_pool<<<dim3(BB, 8), NF>>>(pU, bc5, 5, NF*5, 2*NF);

    // ---- final projection ----
    k_final<<<BB, 256>>>(Wo, bo, out);
}